// round 8
// baseline (speedup 1.0000x reference)
#include <cuda_runtime.h>
#include <math.h>

// SO3_Rotation, pipelined two-kernel scheme (fork-join inside graph capture):
//   dgen(c0) -> [ apply(c0) || dgen(c1) ] -> [ apply(c1) || dgen(c2) ] -> ...
//  A) so3_dgen : 32 elements/block, lane = element; each of 8 warps owns a
//     cost-balanced range of the 165 Wigner-D entries (closed form,
//     template-unrolled), written coalesced to g_D[k*E+e].
//  B) so3_apply: 8 elements per 128-thread block; thread owns 4 channels
//     (float4), computes 25 rows; emb global->reg, D broadcast from smem.

#define NROWS 25
#define NCH   64
#define ETILE 1600
#define NDTOT 165
#define EMAX  50048
#define EPB   8
#define GEPB  32
#define DPITCH 166
#define NCHUNK 4

__device__ float g_D[(size_t)NDTOT * EMAX];

// ---------------- compile-time helpers ----------------
__host__ __device__ constexpr double cfact(int n){ double r=1.0; for(int i=2;i<=n;++i) r*=(double)i; return r; }
__host__ __device__ constexpr double csqrt_(double x){ double r = (x>1.0)?x:1.0; for(int i=0;i<100;++i) r = 0.5*(r + x/r); return r; }
__host__ __device__ constexpr int cmax(int a,int b){ return a>b?a:b; }
__host__ __device__ constexpr int cmin(int a,int b){ return a<b?a:b; }
__host__ __device__ constexpr bool nzB(int x,int y){
    return (x>0&&y>0)||(x<0&&y<0)||(x==0&&y>=0)||(x>0&&y==0);
}
__host__ __device__ constexpr int gL(int g){ return g==0?0 : (g<10?1 : (g<35?2 : (g<84?3 : 4))); }
__host__ __device__ constexpr int gOFF(int g){ int l=gL(g); return l==0?0 : (l==1?1 : (l==2?10 : (l==3?35 : 84))); }

template<int L,int P,int Q,int K,bool Done>
struct DTerm {
    static constexpr float coef = (float)(
        ((((P-Q+K)&1)? -1.0 : 1.0) *
         csqrt_(cfact(L+P)*cfact(L-P)*cfact(L+Q)*cfact(L-Q)) /
         (cfact(L+Q-K)*cfact(K)*cfact(P-Q+K)*cfact(L-P-K))));
    __device__ static __forceinline__ float eval(const float* chp, const float* shp){
        constexpr int K1 = cmin(L+Q, L-P);
        return fmaf(coef, chp[2*L+Q-P-2*K]*shp[P-Q+2*K],
                    DTerm<L,P,Q,K+1,(K+1>K1)>::eval(chp,shp));
    }
};
template<int L,int P,int Q,int K>
struct DTerm<L,P,Q,K,true> {
    __device__ static __forceinline__ float eval(const float*, const float*){ return 0.f; }
};

template<int L,int P,int Q>
__device__ __forceinline__ float dval(const float* chp, const float* shp){
    constexpr int K0 = cmax(0, Q-P);
    constexpr int K1 = cmin(L+Q, L-P);
    return DTerm<L,P,Q,K0,(K0>K1)>::eval(chp,shp);
}

template<int L,int X,int Y>
__device__ __forceinline__ float Bval(const float* chp, const float* shp){
    if constexpr (X>0 && Y>0){
        constexpr float s1 = ((X+Y)&1)? -1.f : 1.f;
        constexpr float s2 = (X&1)? -1.f : 1.f;
        return s1*dval<L,X,Y>(chp,shp) + s2*dval<L,X,-Y>(chp,shp);
    } else if constexpr (X<0 && Y<0){
        constexpr int P=-X, Q=-Y;
        constexpr float s1 = ((P+Q)&1)? -1.f : 1.f;
        constexpr float s2 = (P&1)? -1.f : 1.f;
        return s1*dval<L,P,Q>(chp,shp) - s2*dval<L,P,-Q>(chp,shp);
    } else if constexpr (X==0 && Y==0){
        return dval<L,0,0>(chp,shp);
    } else if constexpr (X==0 && Y>0){
        constexpr float s = ((Y&1)? -1.f : 1.f) * 1.41421356237309515f;
        return s*dval<L,0,Y>(chp,shp);
    } else if constexpr (X>0 && Y==0){
        constexpr float s = ((X&1)? -1.f : 1.f) * 1.41421356237309515f;
        return s*dval<L,X,0>(chp,shp);
    } else {
        return 0.f;
    }
}

struct Trig { float cat[5], sat[5], cgt[5], sgt[5]; };

template<int G>
__device__ __forceinline__ float Dentry(const float* chp, const float* shp, const Trig& T){
    constexpr int L  = gL(G);
    constexpr int IJ = G - gOFF(G);
    constexpr int N1 = 2*L+1;
    constexpr int I = IJ / N1, J = IJ % N1;
    constexpr int MA = I - L, NB = J - L;
    constexpr int P = MA<0 ? -MA : MA;
    constexpr int Q = NB<0 ? -NB : NB;
    float rc = T.cat[P];
    float rs = (MA>0) ? -T.sat[P] : T.sat[P];
    float cc = T.cgt[Q];
    float cs = (NB>0) ? T.sgt[Q] : -T.sgt[Q];
    float acc = 0.f;
    if constexpr (nzB(MA,NB))
        acc = fmaf(rc*cc, Bval<L,MA,NB>(chp,shp), acc);
    if constexpr (NB!=0){ if constexpr (nzB(MA,-NB))
        acc = fmaf(rc*cs, Bval<L,MA,(NB!=0)?-NB:0>(chp,shp), acc); }
    if constexpr (MA!=0){ if constexpr (nzB(-MA,NB))
        acc = fmaf(rs*cc, Bval<L,(MA!=0)?-MA:0,NB>(chp,shp), acc); }
    if constexpr (MA!=0 && NB!=0){ if constexpr (nzB(-MA,-NB))
        acc = fmaf(rs*cs, Bval<L,(MA!=0)?-MA:0,(NB!=0)?-NB:0>(chp,shp), acc); }
    return acc;
}

template<int G,int END,bool Done>
struct DRange {
    __device__ static __forceinline__ void run(float* __restrict__ gbase, size_t sE,
            const float* chp, const float* shp, const Trig& T){
        gbase[(size_t)G * sE] = Dentry<G>(chp, shp, T);
        DRange<G+1,END,(G+1==END)>::run(gbase, sE, chp, shp, T);
    }
};
template<int G,int END>
struct DRange<G,END,true>{
    __device__ static __forceinline__ void run(float*, size_t, const float*, const float*, const Trig&){}
};

// ---------------- kernel A: build D (chunked) ----------------
__global__ void __launch_bounds__(256)
so3_dgen(const float* __restrict__ rot, int eBase, int eEnd, int E)
{
    const int tid  = threadIdx.x;
    const int lane = tid & 31;
    const int w    = tid >> 5;
    const int e    = eBase + blockIdx.x * GEPB + lane;
    if (e >= eEnd) return;

    const float* R = rot + (size_t)e * 9;
    float r00=R[0], r01=R[1], r02=R[2];
    float r11=R[4];
    float r20=R[6], r21=R[7], r22=R[8];

    float x0=r01, x1=r11, x2=r21;
    float inv = rsqrtf(x0*x0 + x1*x1 + x2*x2);
    x0*=inv; x1*=inv; x2*=inv;
    x0 = fminf(1.f, fmaxf(-1.f, x0));
    x1 = fminf(1.f, fmaxf(-1.f, x1));
    x2 = fminf(1.f, fmaxf(-1.f, x2));
    float cb = x1;
    float rxz = sqrtf(x0*x0 + x2*x2);
    float ca, sa;
    if (rxz > 1e-20f){ ca = x2/rxz; sa = x0/rxz; } else { ca = 1.f; sa = 0.f; }
    float gy = ca*r02 - sa*r22;
    float gx = ca*r00 - sa*r20;
    float gr = sqrtf(gx*gx + gy*gy);
    float cg, sg;
    if (gr > 1e-20f){ cg = gx/gr; sg = gy/gr; } else { cg = 1.f; sg = 0.f; }

    float ch = sqrtf(fmaxf(0.f, 0.5f*(1.f+cb)));
    float sh = sqrtf(fmaxf(0.f, 0.5f*(1.f-cb)));
    float chp[9], shp[9];
    chp[0]=1.f; shp[0]=1.f;
    #pragma unroll
    for (int k=1;k<9;k++){ chp[k]=chp[k-1]*ch; shp[k]=shp[k-1]*sh; }

    Trig T;
    T.cat[0]=1.f; T.sat[0]=0.f; T.cgt[0]=1.f; T.sgt[0]=0.f;
    #pragma unroll
    for (int k=1;k<5;k++){
        float c0=T.cat[k-1], s0=T.sat[k-1];
        T.cat[k]=c0*ca - s0*sa;  T.sat[k]=s0*ca + c0*sa;
        float c1=T.cgt[k-1], s1=T.sgt[k-1];
        T.cgt[k]=c1*cg - s1*sg;  T.sgt[k]=s1*cg + c1*sg;
    }

    float* gbase = g_D + e;
    size_t sE = (size_t)E;
    switch (w) {
        case 0: DRange<  0,  35, false>::run(gbase, sE, chp, shp, T); break;
        case 1: DRange< 35,  57, false>::run(gbase, sE, chp, shp, T); break;
        case 2: DRange< 57,  79, false>::run(gbase, sE, chp, shp, T); break;
        case 3: DRange< 79,  97, false>::run(gbase, sE, chp, shp, T); break;
        case 4: DRange< 97, 114, false>::run(gbase, sE, chp, shp, T); break;
        case 5: DRange<114, 131, false>::run(gbase, sE, chp, shp, T); break;
        case 6: DRange<131, 148, false>::run(gbase, sE, chp, shp, T); break;
        default:DRange<148, 165, false>::run(gbase, sE, chp, shp, T); break;
    }
}

// ---------------- kernel B: apply block-diagonal D (chunked) ----------------
template<int L, int B0, int DOFF>
__device__ __forceinline__ void applyL(const float* __restrict__ sDe,
                                       const float* __restrict__ ebase,
                                       float* __restrict__ obase)
{
    constexpr int N1 = 2*L+1;
    float4 eR[N1];
    #pragma unroll
    for (int j=0;j<N1;j++)
        eR[j] = *(const float4*)(ebase + (B0+j)*NCH);
    #pragma unroll
    for (int i=0;i<N1;i++){
        float4 a;
        float d0 = sDe[DOFF + i*N1];
        a.x = d0*eR[0].x; a.y = d0*eR[0].y; a.z = d0*eR[0].z; a.w = d0*eR[0].w;
        #pragma unroll
        for (int j=1;j<N1;j++){
            float d = sDe[DOFF + i*N1 + j];
            a.x = fmaf(d, eR[j].x, a.x);
            a.y = fmaf(d, eR[j].y, a.y);
            a.z = fmaf(d, eR[j].z, a.z);
            a.w = fmaf(d, eR[j].w, a.w);
        }
        *(float4*)(obase + (B0+i)*NCH) = a;
    }
}

__global__ void __launch_bounds__(128)
so3_apply(const float* __restrict__ emb, float* __restrict__ out, int eBase, int E)
{
    __shared__ float sD[EPB * DPITCH];
    const int tid = threadIdx.x;
    const int e0  = eBase + blockIdx.x * EPB;

    #pragma unroll
    for (int idx = tid; idx < EPB * NDTOT; idx += 128) {
        int el = idx & (EPB - 1);
        int k  = idx >> 3;
        sD[el * DPITCH + k] = g_D[(size_t)k * E + e0 + el];
    }
    __syncthreads();

    const int el     = tid >> 4;
    const int lane16 = tid & 15;
    const float* sDe = sD + el * DPITCH;
    const size_t off = (size_t)(e0 + el) * ETILE + lane16 * 4;
    const float* eb  = emb + off;
    float*       ob  = out + off;

    applyL<4,16, 84>(sDe, eb, ob);
    applyL<3, 9, 35>(sDe, eb, ob);
    applyL<2, 4, 10>(sDe, eb, ob);
    applyL<1, 1,  1>(sDe, eb, ob);
    applyL<0, 0,  0>(sDe, eb, ob);
}

extern "C" void kernel_launch(void* const* d_in, const int* in_sizes, int n_in,
                              void* d_out, int out_size)
{
    const float* rot = (const float*)d_in[0];   // (E,3,3)
    const float* emb = (const float*)d_in[1];   // (E,25,64)
    float* out = (float*)d_out;                 // (E,25,64)
    int E = in_sizes[0] / 9;

    // chunk size: multiple of 32 (covers GEPB and EPB alignment)
    int chunk = ((E + NCHUNK - 1) / NCHUNK + 31) & ~31;

    cudaStream_t s2;
    cudaStreamCreate(&s2);

    // dgen(chunk 0) on the main (capture) stream
    {
        int g1 = E < chunk ? E : chunk;
        so3_dgen<<<(g1 + GEPB - 1) / GEPB, 256>>>(rot, 0, g1, E);
    }

    for (int c = 0; c < NCHUNK; c++) {
        int a0 = c * chunk;
        if (a0 >= E) break;
        int a1 = (c + 1) * chunk; if (a1 > E) a1 = E;

        // fork: dgen(chunk c+1) on s2, concurrent with apply(chunk c)
        cudaEvent_t evF = 0, evJ = 0;
        int g0 = (c + 1) * chunk;
        if (g0 < E) {
            int g1 = (c + 2) * chunk; if (g1 > E) g1 = E;
            cudaEventCreateWithFlags(&evF, cudaEventDisableTiming);
            cudaEventRecord(evF, 0);
            cudaStreamWaitEvent(s2, evF, 0);
            so3_dgen<<<(g1 - g0 + GEPB - 1) / GEPB, 256, 0, s2>>>(rot, g0, g1, E);
            cudaEventCreateWithFlags(&evJ, cudaEventDisableTiming);
            cudaEventRecord(evJ, s2);
        }

        so3_apply<<<(a1 - a0 + EPB - 1) / EPB, 128>>>(emb, out, a0, E);

        if (evJ) { cudaStreamWaitEvent(0, evJ, 0); cudaEventDestroy(evJ); }
        if (evF) cudaEventDestroy(evF);
    }

    cudaStreamDestroy(s2);
}

// round 9
// speedup vs baseline: 1.2018x; 1.2018x over previous
#include <cuda_runtime.h>
#include <math.h>

// SO3_Rotation, single fused kernel:
//   128 threads / 8 elements per block.
//   Phase 1 (threads 0..63): element = tid>>3, slot = tid&7; each slot computes
//     a cost-balanced ~1/8 range of the 165 Wigner-D entries in closed form
//     (template-unrolled, compile-time coefficients) into shared memory.
//     Short per-thread chains keep register pressure near the apply path's.
//   Phase 2 (all 128): element = tid>>4, thread owns 4 channels (float4),
//     computes all 25 output rows; emb global->reg, D broadcast from smem.

#define NROWS 25
#define NCH   64
#define ETILE 1600
#define NDTOT 165
#define EPB   8
#define DPITCH 166

// ---------------- compile-time helpers ----------------
__host__ __device__ constexpr double cfact(int n){ double r=1.0; for(int i=2;i<=n;++i) r*=(double)i; return r; }
__host__ __device__ constexpr double csqrt_(double x){ double r = (x>1.0)?x:1.0; for(int i=0;i<100;++i) r = 0.5*(r + x/r); return r; }
__host__ __device__ constexpr int cmax(int a,int b){ return a>b?a:b; }
__host__ __device__ constexpr int cmin(int a,int b){ return a<b?a:b; }
__host__ __device__ constexpr bool nzB(int x,int y){
    return (x>0&&y>0)||(x<0&&y<0)||(x==0&&y>=0)||(x>0&&y==0);
}
__host__ __device__ constexpr int gL(int g){ return g==0?0 : (g<10?1 : (g<35?2 : (g<84?3 : 4))); }
__host__ __device__ constexpr int gOFF(int g){ int l=gL(g); return l==0?0 : (l==1?1 : (l==2?10 : (l==3?35 : 84))); }

template<int L,int P,int Q,int K,bool Done>
struct DTerm {
    static constexpr float coef = (float)(
        ((((P-Q+K)&1)? -1.0 : 1.0) *
         csqrt_(cfact(L+P)*cfact(L-P)*cfact(L+Q)*cfact(L-Q)) /
         (cfact(L+Q-K)*cfact(K)*cfact(P-Q+K)*cfact(L-P-K))));
    __device__ static __forceinline__ float eval(const float* chp, const float* shp){
        constexpr int K1 = cmin(L+Q, L-P);
        return fmaf(coef, chp[2*L+Q-P-2*K]*shp[P-Q+2*K],
                    DTerm<L,P,Q,K+1,(K+1>K1)>::eval(chp,shp));
    }
};
template<int L,int P,int Q,int K>
struct DTerm<L,P,Q,K,true> {
    __device__ static __forceinline__ float eval(const float*, const float*){ return 0.f; }
};

template<int L,int P,int Q>
__device__ __forceinline__ float dval(const float* chp, const float* shp){
    constexpr int K0 = cmax(0, Q-P);
    constexpr int K1 = cmin(L+Q, L-P);
    return DTerm<L,P,Q,K0,(K0>K1)>::eval(chp,shp);
}

template<int L,int X,int Y>
__device__ __forceinline__ float Bval(const float* chp, const float* shp){
    if constexpr (X>0 && Y>0){
        constexpr float s1 = ((X+Y)&1)? -1.f : 1.f;
        constexpr float s2 = (X&1)? -1.f : 1.f;
        return s1*dval<L,X,Y>(chp,shp) + s2*dval<L,X,-Y>(chp,shp);
    } else if constexpr (X<0 && Y<0){
        constexpr int P=-X, Q=-Y;
        constexpr float s1 = ((P+Q)&1)? -1.f : 1.f;
        constexpr float s2 = (P&1)? -1.f : 1.f;
        return s1*dval<L,P,Q>(chp,shp) - s2*dval<L,P,-Q>(chp,shp);
    } else if constexpr (X==0 && Y==0){
        return dval<L,0,0>(chp,shp);
    } else if constexpr (X==0 && Y>0){
        constexpr float s = ((Y&1)? -1.f : 1.f) * 1.41421356237309515f;
        return s*dval<L,0,Y>(chp,shp);
    } else if constexpr (X>0 && Y==0){
        constexpr float s = ((X&1)? -1.f : 1.f) * 1.41421356237309515f;
        return s*dval<L,X,0>(chp,shp);
    } else {
        return 0.f;
    }
}

struct Trig { float cat[5], sat[5], cgt[5], sgt[5]; };

template<int G>
__device__ __forceinline__ float Dentry(const float* chp, const float* shp, const Trig& T){
    constexpr int L  = gL(G);
    constexpr int IJ = G - gOFF(G);
    constexpr int N1 = 2*L+1;
    constexpr int I = IJ / N1, J = IJ % N1;
    constexpr int MA = I - L, NB = J - L;
    constexpr int P = MA<0 ? -MA : MA;
    constexpr int Q = NB<0 ? -NB : NB;
    float rc = T.cat[P];
    float rs = (MA>0) ? -T.sat[P] : T.sat[P];
    float cc = T.cgt[Q];
    float cs = (NB>0) ? T.sgt[Q] : -T.sgt[Q];
    float acc = 0.f;
    if constexpr (nzB(MA,NB))
        acc = fmaf(rc*cc, Bval<L,MA,NB>(chp,shp), acc);
    if constexpr (NB!=0){ if constexpr (nzB(MA,-NB))
        acc = fmaf(rc*cs, Bval<L,MA,(NB!=0)?-NB:0>(chp,shp), acc); }
    if constexpr (MA!=0){ if constexpr (nzB(-MA,NB))
        acc = fmaf(rs*cc, Bval<L,(MA!=0)?-MA:0,NB>(chp,shp), acc); }
    if constexpr (MA!=0 && NB!=0){ if constexpr (nzB(-MA,-NB))
        acc = fmaf(rs*cs, Bval<L,(MA!=0)?-MA:0,(NB!=0)?-NB:0>(chp,shp), acc); }
    return acc;
}

template<int G,int END,bool Done>
struct DRangeS {
    __device__ static __forceinline__ void run(float* __restrict__ sbase,
            const float* chp, const float* shp, const Trig& T){
        sbase[G] = Dentry<G>(chp, shp, T);
        DRangeS<G+1,END,(G+1==END)>::run(sbase, chp, shp, T);
    }
};
template<int G,int END>
struct DRangeS<G,END,true>{
    __device__ static __forceinline__ void run(float*, const float*, const float*, const Trig&){}
};

// ---------------- apply helper ----------------
template<int L, int B0, int DOFF>
__device__ __forceinline__ void applyL(const float* __restrict__ sDe,
                                       const float* __restrict__ ebase,
                                       float* __restrict__ obase)
{
    constexpr int N1 = 2*L+1;
    float4 eR[N1];
    #pragma unroll
    for (int j=0;j<N1;j++)
        eR[j] = *(const float4*)(ebase + (B0+j)*NCH);
    #pragma unroll
    for (int i=0;i<N1;i++){
        float4 a;
        float d0 = sDe[DOFF + i*N1];
        a.x = d0*eR[0].x; a.y = d0*eR[0].y; a.z = d0*eR[0].z; a.w = d0*eR[0].w;
        #pragma unroll
        for (int j=1;j<N1;j++){
            float d = sDe[DOFF + i*N1 + j];
            a.x = fmaf(d, eR[j].x, a.x);
            a.y = fmaf(d, eR[j].y, a.y);
            a.z = fmaf(d, eR[j].z, a.z);
            a.w = fmaf(d, eR[j].w, a.w);
        }
        *(float4*)(obase + (B0+i)*NCH) = a;
    }
}

// ---------------- fused kernel ----------------
__global__ void __launch_bounds__(128)
so3_fused(const float* __restrict__ rot,
          const float* __restrict__ emb,
          float* __restrict__ out, int E)
{
    __shared__ float sD[EPB * DPITCH];
    const int tid = threadIdx.x;
    const int e0  = blockIdx.x * EPB;

    // ---- phase 1: threads 0..63 build D (element = tid>>3, slot = tid&7) ----
    if (tid < 64) {
        const int gel  = tid >> 3;
        const int slot = tid & 7;
        const int e    = e0 + gel;
        if (e < E) {
            const float* R = rot + (size_t)e * 9;
            float r00=R[0], r01=R[1], r02=R[2];
            float r11=R[4];
            float r20=R[6], r21=R[7], r22=R[8];

            float x0=r01, x1=r11, x2=r21;
            float inv = rsqrtf(x0*x0 + x1*x1 + x2*x2);
            x0*=inv; x1*=inv; x2*=inv;
            x0 = fminf(1.f, fmaxf(-1.f, x0));
            x1 = fminf(1.f, fmaxf(-1.f, x1));
            x2 = fminf(1.f, fmaxf(-1.f, x2));
            float cb = x1;
            float rxz = sqrtf(x0*x0 + x2*x2);
            float ca, sa;
            if (rxz > 1e-20f){ ca = x2/rxz; sa = x0/rxz; } else { ca = 1.f; sa = 0.f; }
            float gy = ca*r02 - sa*r22;
            float gx = ca*r00 - sa*r20;
            float gr = sqrtf(gx*gx + gy*gy);
            float cg, sg;
            if (gr > 1e-20f){ cg = gx/gr; sg = gy/gr; } else { cg = 1.f; sg = 0.f; }

            float ch = sqrtf(fmaxf(0.f, 0.5f*(1.f+cb)));
            float sh = sqrtf(fmaxf(0.f, 0.5f*(1.f-cb)));
            float chp[9], shp[9];
            chp[0]=1.f; shp[0]=1.f;
            #pragma unroll
            for (int k=1;k<9;k++){ chp[k]=chp[k-1]*ch; shp[k]=shp[k-1]*sh; }

            Trig T;
            T.cat[0]=1.f; T.sat[0]=0.f; T.cgt[0]=1.f; T.sgt[0]=0.f;
            #pragma unroll
            for (int k=1;k<5;k++){
                float c0=T.cat[k-1], s0=T.sat[k-1];
                T.cat[k]=c0*ca - s0*sa;  T.sat[k]=s0*ca + c0*sa;
                float c1=T.cgt[k-1], s1=T.sgt[k-1];
                T.cgt[k]=c1*cg - s1*sg;  T.sgt[k]=s1*cg + c1*sg;
            }

            float* sbase = sD + gel * DPITCH;
            // 8 cost-balanced entry ranges (cost ~ 2L+1 per entry)
            switch (slot) {
                case 0: DRangeS<  0,  35, false>::run(sbase, chp, shp, T); break;
                case 1: DRangeS< 35,  57, false>::run(sbase, chp, shp, T); break;
                case 2: DRangeS< 57,  79, false>::run(sbase, chp, shp, T); break;
                case 3: DRangeS< 79,  97, false>::run(sbase, chp, shp, T); break;
                case 4: DRangeS< 97, 114, false>::run(sbase, chp, shp, T); break;
                case 5: DRangeS<114, 131, false>::run(sbase, chp, shp, T); break;
                case 6: DRangeS<131, 148, false>::run(sbase, chp, shp, T); break;
                default:DRangeS<148, 165, false>::run(sbase, chp, shp, T); break;
            }
        }
    }
    __syncthreads();

    // ---- phase 2: apply (element = tid>>4, 4 channels per thread) ----
    const int el     = tid >> 4;
    const int lane16 = tid & 15;
    const int e      = e0 + el;
    if (e >= E) return;
    const float* sDe = sD + el * DPITCH;
    const size_t off = (size_t)e * ETILE + lane16 * 4;
    const float* eb  = emb + off;
    float*       ob  = out + off;

    applyL<4,16, 84>(sDe, eb, ob);
    applyL<3, 9, 35>(sDe, eb, ob);
    applyL<2, 4, 10>(sDe, eb, ob);
    applyL<1, 1,  1>(sDe, eb, ob);
    applyL<0, 0,  0>(sDe, eb, ob);
}

extern "C" void kernel_launch(void* const* d_in, const int* in_sizes, int n_in,
                              void* d_out, int out_size)
{
    const float* rot = (const float*)d_in[0];   // (E,3,3)
    const float* emb = (const float*)d_in[1];   // (E,25,64)
    float* out = (float*)d_out;                 // (E,25,64)
    int E = in_sizes[0] / 9;
    so3_fused<<<(E + EPB - 1) / EPB, 128>>>(rot, emb, out, E);
}